// round 2
// baseline (speedup 1.0000x reference)
#include <cuda_runtime.h>

// LinearAttention fused kernel, fp32 FFMA2 version.
// x: [8][128][16384], w_qkv: [384][128], w_out: [128][128], b_out: [128]
// y: [8][128][16384]

#define BB 8
#define CC 128
#define NN 16384
#define NT 128          // n-tile per block
#define NBLK (NN / NT)  // 128 blocks per batch for K1/K4
#define PITCH 130       // padded smem pitch (even => 8B aligned cols, conflict-free)

// -------- scratch (device globals; allocation-free rule) --------
__device__ float g_Spart[BB][NBLK][128][128];  // 67 MB
__device__ float g_Zpart[BB][NBLK][128];
__device__ float g_Shat[BB][128][128];
__device__ float g_C2[BB][128][128];           // C2cat[b][o][j], j = h*32+d
__device__ float g_A[BB][128][128];

// -------- packed f32x2 helpers (Blackwell FFMA2) --------
__device__ __forceinline__ unsigned long long pack2(float lo, float hi) {
    unsigned long long r;
    asm("mov.b64 %0, {%1, %2};" : "=l"(r) : "f"(lo), "f"(hi));
    return r;
}
__device__ __forceinline__ void fma2(unsigned long long& d,
                                     unsigned long long a,
                                     unsigned long long b) {
    asm("fma.rn.f32x2 %0, %1, %2, %0;" : "+l"(d) : "l"(a), "l"(b));
}
__device__ __forceinline__ float2 unpack2(unsigned long long v) {
    float2 f;
    asm("mov.b64 {%0, %1}, %2;" : "=f"(f.x), "=f"(f.y) : "l"(v));
    return f;
}

// =====================================================================
// K1: per (batch, n-tile): k = Wk@x ; E = exp(k) ; Spart = E@x^T ; Zpart
// =====================================================================
#define SMEM_K1 ((2 * 128 * PITCH + 128 * 128) * 4)

__global__ void __launch_bounds__(256, 1)
k1_kernel(const float* __restrict__ x, const float* __restrict__ wqkv) {
    extern __shared__ float sm[];
    float* Wk_t = sm;                     // [c][r] pitch PITCH
    float* X_t  = sm + 128 * PITCH;       // [n][c] pitch PITCH
    float* E_s  = sm + 2 * 128 * PITCH;   // [r][n] pitch 128

    const int b   = blockIdx.y;
    const int blk = blockIdx.x;
    const int tid = threadIdx.x;
    const int tx  = tid & 15;
    const int ty  = tid >> 4;
    const int n0  = blk * NT;

    const float* xb = x + (size_t)b * CC * NN;

    // load Wk transposed: Wk_t[c][r] = w_qkv[128+r][c]
    for (int i = tid; i < 128 * 128; i += 256) {
        int r = i >> 7, c = i & 127;
        Wk_t[c * PITCH + r] = wqkv[(128 + r) * 128 + c];
    }
    // load X transposed: X_t[n][c] = x[b][c][n0+n]
    for (int q = tid; q < 128 * 32; q += 256) {
        int c = q >> 5, j4 = (q & 31) * 4;
        float4 v = *(const float4*)(xb + (size_t)c * NN + n0 + j4);
        X_t[(j4 + 0) * PITCH + c] = v.x;
        X_t[(j4 + 1) * PITCH + c] = v.y;
        X_t[(j4 + 2) * PITCH + c] = v.z;
        X_t[(j4 + 3) * PITCH + c] = v.w;
    }
    __syncthreads();

    // ---- stage 1: k[r][n] = sum_c Wk[r][c] * X[c][n], rows pair-packed ----
    // thread rows: r = ty*2 + 32*i2 (+1), cols: n = tx + 16*j
    unsigned long long acc1[4][8];
#pragma unroll
    for (int i2 = 0; i2 < 4; i2++)
#pragma unroll
        for (int j = 0; j < 8; j++) acc1[i2][j] = 0ULL;

#pragma unroll 4
    for (int c = 0; c < 128; c++) {
        unsigned long long a2[4];
        float bv[8];
#pragma unroll
        for (int i2 = 0; i2 < 4; i2++)
            a2[i2] = *(const unsigned long long*)&Wk_t[c * PITCH + ty * 2 + 32 * i2];
#pragma unroll
        for (int j = 0; j < 8; j++) bv[j] = X_t[(tx + 16 * j) * PITCH + c];
#pragma unroll
        for (int j = 0; j < 8; j++) {
            unsigned long long bd = pack2(bv[j], bv[j]);
#pragma unroll
            for (int i2 = 0; i2 < 4; i2++) fma2(acc1[i2][j], a2[i2], bd);
        }
    }

    // ---- exp epilogue: E to smem, Z accumulation ----
    float zacc[8];
#pragma unroll
    for (int i = 0; i < 8; i++) zacc[i] = 0.f;
#pragma unroll
    for (int i2 = 0; i2 < 4; i2++) {
        int r0 = ty * 2 + 32 * i2;
#pragma unroll
        for (int j = 0; j < 8; j++) {
            float2 kv = unpack2(acc1[i2][j]);
            float e0 = __expf(kv.x);
            float e1 = __expf(kv.y);
            int n = tx + 16 * j;
            E_s[r0 * 128 + n]       = e0;
            E_s[(r0 + 1) * 128 + n] = e1;
            zacc[2 * i2]     += e0;
            zacc[2 * i2 + 1] += e1;
        }
    }
    __syncthreads();

    // ---- stage 2: S[r][c] = sum_n E[r][n] * X[c][n], cols pair-packed ----
    // thread rows: r = ty + 16*i, cols: c = tx*2 + 32*j2 (+1)
    unsigned long long acc2[8][4];
#pragma unroll
    for (int i = 0; i < 8; i++)
#pragma unroll
        for (int j2 = 0; j2 < 4; j2++) acc2[i][j2] = 0ULL;

#pragma unroll 4
    for (int nk = 0; nk < 128; nk++) {
        float av[8];
        unsigned long long b2[4];
#pragma unroll
        for (int i = 0; i < 8; i++) av[i] = E_s[(ty + 16 * i) * 128 + nk];
#pragma unroll
        for (int j2 = 0; j2 < 4; j2++)
            b2[j2] = *(const unsigned long long*)&X_t[nk * PITCH + tx * 2 + 32 * j2];
#pragma unroll
        for (int i = 0; i < 8; i++) {
            unsigned long long ad = pack2(av[i], av[i]);
#pragma unroll
            for (int j2 = 0; j2 < 4; j2++) fma2(acc2[i][j2], ad, b2[j2]);
        }
    }

    // write S partial (coalesced float2)
#pragma unroll
    for (int i = 0; i < 8; i++) {
        int r = ty + 16 * i;
#pragma unroll
        for (int j2 = 0; j2 < 4; j2++) {
            float2 v = unpack2(acc2[i][j2]);
            *(float2*)&g_Spart[b][blk][r][tx * 2 + 32 * j2] = v;
        }
    }

    // Z reduce across the 16 tx lanes via smem (reuse E_s)
    __syncthreads();
    float* Zred = E_s;  // [128][16]
#pragma unroll
    for (int i2 = 0; i2 < 4; i2++) {
        int r0 = ty * 2 + 32 * i2;
        Zred[r0 * 16 + tx]       = zacc[2 * i2];
        Zred[(r0 + 1) * 16 + tx] = zacc[2 * i2 + 1];
    }
    __syncthreads();
    if (tid < 128) {
        float z = 0.f;
#pragma unroll
        for (int k = 0; k < 16; k++) z += Zred[tid * 16 + k];
        g_Zpart[b][blk][tid] = z;
    }
}

// =====================================================================
// KR: reduce partials, normalize: Shat[b][r][c] = sum_p Spart / sum_p Zpart
// =====================================================================
__global__ void __launch_bounds__(128)
kr_kernel() {
    const int b = blockIdx.x >> 7;
    const int r = blockIdx.x & 127;
    const int c = threadIdx.x;
    float z = 0.f;
    for (int p = 0; p < NBLK; p++) z += g_Zpart[b][p][r];
    float s = 0.f;
    for (int p = 0; p < NBLK; p++) s += g_Spart[b][p][r][c];
    g_Shat[b][r][c] = s / z;
}

// =====================================================================
// K2: per (b,h): ctx[d][e] = sum_c Shat_h[d][c]*Wv_h[e][c];
//                C2[o][h*32+d] = sum_e w_out[o][h*32+e]*ctx[d][e]
// =====================================================================
__global__ void __launch_bounds__(128)
k2_kernel(const float* __restrict__ wqkv, const float* __restrict__ wout) {
    const int b = blockIdx.x >> 2;
    const int h = blockIdx.x & 3;
    __shared__ float Sh[32][129];
    __shared__ float Wv[32][129];
    __shared__ float ctx[32][33];
    const int tid = threadIdx.x;

    for (int i = tid; i < 32 * 128; i += 128) {
        int d = i >> 7, c = i & 127;
        Sh[d][c] = g_Shat[b][h * 32 + d][c];
        Wv[d][c] = wqkv[(256 + h * 32 + d) * 128 + c];
    }
    __syncthreads();
    for (int u = tid; u < 1024; u += 128) {
        int d = u >> 5, e = u & 31;
        float s = 0.f;
#pragma unroll 4
        for (int c = 0; c < 128; c++) s += Sh[d][c] * Wv[e][c];
        ctx[d][e] = s;
    }
    __syncthreads();
    float wo[32];
#pragma unroll
    for (int e = 0; e < 32; e++) wo[e] = wout[tid * 128 + h * 32 + e];
    for (int d = 0; d < 32; d++) {
        float s = 0.f;
#pragma unroll
        for (int e = 0; e < 32; e++) s += wo[e] * ctx[d][e];
        g_C2[b][tid][h * 32 + d] = s;
    }
}

// =====================================================================
// K3: A[b] = C2cat[b] @ Wq  ([128,128] @ [128,128]), c-chunks of 32
// =====================================================================
#define SMEM_K3 ((128 * 129 + 128 * 32) * 4)
__global__ void __launch_bounds__(256)
k3_kernel(const float* __restrict__ wqkv) {
    extern __shared__ float sm3[];
    float* C2s = sm3;               // [128][129]
    float* Wqs = sm3 + 128 * 129;   // [128][32]
    const int b = blockIdx.x;
    const int chunk = blockIdx.y;
    const int tid = threadIdx.x;

    for (int i = tid; i < 128 * 128; i += 256) {
        int o = i >> 7, j = i & 127;
        C2s[o * 129 + j] = g_C2[b][o][j];
    }
    for (int i = tid; i < 128 * 32; i += 256) {
        int j = i >> 5, cc = i & 31;
        Wqs[j * 32 + cc] = wqkv[j * 128 + chunk * 32 + cc];
    }
    __syncthreads();

    const int o  = tid & 127;
    const int cg = tid >> 7;  // 0..1
    float acc[16];
#pragma unroll
    for (int i = 0; i < 16; i++) acc[i] = 0.f;
#pragma unroll 4
    for (int j = 0; j < 128; j++) {
        float a = C2s[o * 129 + j];
#pragma unroll
        for (int i = 0; i < 16; i++) acc[i] += a * Wqs[j * 32 + cg * 16 + i];
    }
#pragma unroll
    for (int i = 0; i < 16; i++)
        g_A[b][o][chunk * 32 + cg * 16 + i] = acc[i];
}

// =====================================================================
// K4: y[b][o][n] = sum_c A[b][o][c] * x[b][c][n] + b_out[o]
// =====================================================================
#define SMEM_K4 (2 * 128 * PITCH * 4)
__global__ void __launch_bounds__(256, 1)
k4_kernel(const float* __restrict__ x, const float* __restrict__ bias,
          float* __restrict__ y) {
    extern __shared__ float sm4[];
    float* A_t = sm4;               // [c][o] pitch PITCH
    float* X_t = sm4 + 128 * PITCH; // [n][c] pitch PITCH

    const int b   = blockIdx.y;
    const int blk = blockIdx.x;
    const int tid = threadIdx.x;
    const int tx  = tid & 15;
    const int ty  = tid >> 4;
    const int n0  = blk * NT;

    const float* xb = x + (size_t)b * CC * NN;

    for (int i = tid; i < 128 * 128; i += 256) {
        int o = i >> 7, c = i & 127;
        A_t[c * PITCH + o] = g_A[b][o][c];
    }
    for (int q = tid; q < 128 * 32; q += 256) {
        int c = q >> 5, j4 = (q & 31) * 4;
        float4 v = *(const float4*)(xb + (size_t)c * NN + n0 + j4);
        X_t[(j4 + 0) * PITCH + c] = v.x;
        X_t[(j4 + 1) * PITCH + c] = v.y;
        X_t[(j4 + 2) * PITCH + c] = v.z;
        X_t[(j4 + 3) * PITCH + c] = v.w;
    }
    __syncthreads();

    unsigned long long acc[4][8];
#pragma unroll
    for (int i2 = 0; i2 < 4; i2++)
#pragma unroll
        for (int j = 0; j < 8; j++) acc[i2][j] = 0ULL;

#pragma unroll 4
    for (int c = 0; c < 128; c++) {
        unsigned long long a2[4];
        float bv[8];
#pragma unroll
        for (int i2 = 0; i2 < 4; i2++)
            a2[i2] = *(const unsigned long long*)&A_t[c * PITCH + ty * 2 + 32 * i2];
#pragma unroll
        for (int j = 0; j < 8; j++) bv[j] = X_t[(tx + 16 * j) * PITCH + c];
#pragma unroll
        for (int j = 0; j < 8; j++) {
            unsigned long long bd = pack2(bv[j], bv[j]);
#pragma unroll
            for (int i2 = 0; i2 < 4; i2++) fma2(acc[i2][j], a2[i2], bd);
        }
    }

    float* yb = y + (size_t)b * CC * NN;
#pragma unroll
    for (int i2 = 0; i2 < 4; i2++) {
        int r0 = ty * 2 + 32 * i2;
        float b0 = bias[r0];
        float b1 = bias[r0 + 1];
#pragma unroll
        for (int j = 0; j < 8; j++) {
            float2 v = unpack2(acc[i2][j]);
            int n = n0 + tx + 16 * j;
            yb[(size_t)r0 * NN + n]       = v.x + b0;
            yb[(size_t)(r0 + 1) * NN + n] = v.y + b1;
        }
    }
}

// =====================================================================
extern "C" void kernel_launch(void* const* d_in, const int* in_sizes, int n_in,
                              void* d_out, int out_size) {
    (void)in_sizes; (void)n_in; (void)out_size;
    const float* x    = (const float*)d_in[0];
    const float* wqkv = (const float*)d_in[1];
    const float* wout = (const float*)d_in[2];
    const float* bout = (const float*)d_in[3];
    float* y = (float*)d_out;

    cudaFuncSetAttribute(k1_kernel, cudaFuncAttributeMaxDynamicSharedMemorySize, SMEM_K1);
    cudaFuncSetAttribute(k3_kernel, cudaFuncAttributeMaxDynamicSharedMemorySize, SMEM_K3);
    cudaFuncSetAttribute(k4_kernel, cudaFuncAttributeMaxDynamicSharedMemorySize, SMEM_K4);

    k1_kernel<<<dim3(NBLK, BB), 256, SMEM_K1>>>(x, wqkv);
    kr_kernel<<<BB * 128, 128>>>();
    k2_kernel<<<BB * 4, 128>>>(wqkv, wout);
    k3_kernel<<<dim3(BB, 4), 256, SMEM_K3>>>(wqkv);
    k4_kernel<<<dim3(NBLK, BB), 256, SMEM_K4>>>(x, bout, y);
}

// round 6
// speedup vs baseline: 1.3008x; 1.3008x over previous
#include <cuda_runtime.h>
#include <cuda_fp16.h>
#include <stdint.h>

// LinearAttention via warp-level mma.sync (sm_100 plain target; tcgen05 unavailable).
// x: [8][128][16384], w_qkv: [384][128], w_out: [128][128], b_out: [128] -> y: [8][128][16384]

#define BB 8
#define CC 128
#define NN 16384
#define K1_NT 256
#define K1_NBLK (NN / K1_NT)   // 64
#define PH 136                 // smem pitch in halves (272B -> conflict-free frag loads)

__device__ float g_Spart[BB][K1_NBLK][128][128];  // 33.5 MB
__device__ float g_Zpart[BB][K1_NBLK][128];
__device__ float g_Shat[BB][128][128];
__device__ float g_C2[BB][128][128];
__device__ float g_A[BB][128][128];

// ---------------- helpers ----------------
__device__ __forceinline__ uint32_t pck(__half a, __half b) {
    return (uint32_t)*(unsigned short*)&a | ((uint32_t)*(unsigned short*)&b << 16);
}
__device__ __forceinline__ void split_h(float f, __half& h, __half& l) {
    h = __float2half_rn(f);
    l = __float2half_rn(f - __half2float(h));
}
__device__ __forceinline__ uint32_t ldsm(const __half* base, int r, int c) {
    return *(const uint32_t*)(base + r * PH + c);
}
// D += A(16x16) @ B(16x8), f16 in, f32 accum
__device__ __forceinline__ void mma_f16(float* d, uint32_t a0, uint32_t a1, uint32_t a2,
                                        uint32_t a3, uint32_t b0, uint32_t b1) {
    asm volatile(
        "mma.sync.aligned.m16n8k16.row.col.f32.f16.f16.f32 "
        "{%0,%1,%2,%3}, {%4,%5,%6,%7}, {%8,%9}, {%0,%1,%2,%3};"
        : "+f"(d[0]), "+f"(d[1]), "+f"(d[2]), "+f"(d[3])
        : "r"(a0), "r"(a1), "r"(a2), "r"(a3), "r"(b0), "r"(b1));
}

// fp32 128x128 matrix (row-major, row stride 128) -> smem hi/lo [r][c] pitch PH
__device__ void load_mat(const float* __restrict__ m, __half* Mh, __half* Ml, int tid) {
    for (int idx = tid; idx < 4096; idx += 256) {
        int r = idx >> 5, c4 = (idx & 31) * 4;
        float4 v = *(const float4*)(m + r * 128 + c4);
        __half h0, l0, h1, l1, h2, l2, h3, l3;
        split_h(v.x, h0, l0); split_h(v.y, h1, l1);
        split_h(v.z, h2, l2); split_h(v.w, h3, l3);
        *(uint32_t*)&Mh[r * PH + c4]     = pck(h0, h1);
        *(uint32_t*)&Mh[r * PH + c4 + 2] = pck(h2, h3);
        *(uint32_t*)&Ml[r * PH + c4]     = pck(l0, l1);
        *(uint32_t*)&Ml[r * PH + c4 + 2] = pck(l2, l3);
    }
}

// x[b] fp32 [c][NN] tile (128c x 128n at n0) -> XT[n][c] hi/lo (+ optional XN[c][n] hi/lo)
template <bool WANT_XN>
__device__ void load_x(const float* __restrict__ xb, int n0,
                       __half* XTh, __half* XTl, __half* XNh, __half* XNl, int tid) {
    for (int idx = tid; idx < 4096; idx += 256) {
        int c = idx >> 5, n4 = (idx & 31) * 4;
        float4 v = *(const float4*)(xb + (size_t)c * NN + n0 + n4);
        __half h[4], l[4];
        split_h(v.x, h[0], l[0]); split_h(v.y, h[1], l[1]);
        split_h(v.z, h[2], l[2]); split_h(v.w, h[3], l[3]);
#pragma unroll
        for (int m = 0; m < 4; m++) {
            XTh[(n4 + m) * PH + c] = h[m];
            XTl[(n4 + m) * PH + c] = l[m];
        }
        if (WANT_XN) {
            *(uint32_t*)&XNh[c * PH + n4]     = pck(h[0], h[1]);
            *(uint32_t*)&XNh[c * PH + n4 + 2] = pck(h[2], h[3]);
            *(uint32_t*)&XNl[c * PH + n4]     = pck(l[0], l[1]);
            *(uint32_t*)&XNl[c * PH + n4 + 2] = pck(l[2], l[3]);
        }
    }
}

// 3-term split GEMM step for one warp row-band: D[t] += A(rows r0..r0+15, k16 ks) @ B(cols t*8..)
#define FRAG_A(Mh, Ml, r0, kc) \
    uint32_t ah0 = ldsm(Mh, (r0) + g, kc), ah1 = ldsm(Mh, (r0) + g + 8, kc); \
    uint32_t ah2 = ldsm(Mh, (r0) + g, (kc) + 8), ah3 = ldsm(Mh, (r0) + g + 8, (kc) + 8); \
    uint32_t al0 = ldsm(Ml, (r0) + g, kc), al1 = ldsm(Ml, (r0) + g + 8, kc); \
    uint32_t al2 = ldsm(Ml, (r0) + g, (kc) + 8), al3 = ldsm(Ml, (r0) + g + 8, (kc) + 8);

// ---------------- K1 ----------------
// per (b, 256-n tile): k = Wk@x ; E = exp(k) ; S += E@x^T (reg accum) ; Z rowsums
#define SM_WH 0
#define SM_WL (128 * PH)
#define SM_EH (2 * 128 * PH)   // XT then E (aliased)
#define SM_EL (3 * 128 * PH)
#define SM_NH (4 * 128 * PH)
#define SM_NL (5 * 128 * PH)
#define SMEM_K1 (6 * 128 * PH * 2)   // bytes = 208896

__global__ void __launch_bounds__(256, 1)
k1_kernel(const float* __restrict__ x, const float* __restrict__ wqkv) {
    extern __shared__ __half smh[];
    __half* Wh = smh + SM_WH;  __half* Wl = smh + SM_WL;
    __half* Eh = smh + SM_EH;  __half* El = smh + SM_EL;   // XT during stage1
    __half* Nh = smh + SM_NH;  __half* Nl = smh + SM_NL;

    const int tid = threadIdx.x, lane = tid & 31;
    const int g = lane >> 2, tg = lane & 3;
    const int r0 = (tid >> 5) * 16;
    const int b = blockIdx.y, blk = blockIdx.x;
    const float* xb = x + (size_t)b * CC * NN;

    load_mat(wqkv + 128 * 128, Wh, Wl, tid);   // Wk rows

    float SD[16][4];
#pragma unroll
    for (int t = 0; t < 16; t++)
#pragma unroll
        for (int i = 0; i < 4; i++) SD[t][i] = 0.f;
    float zacc0 = 0.f, zacc8 = 0.f;

    for (int sub = 0; sub < 2; sub++) {
        __syncthreads();
        load_x<true>(xb, blk * K1_NT + sub * 128, Eh, El, Nh, Nl, tid);  // XT into E-region
        __syncthreads();

        // stage 1: D = Wk @ X  (B = XT[n][c], k=c)
        float D[16][4];
#pragma unroll
        for (int t = 0; t < 16; t++)
#pragma unroll
            for (int i = 0; i < 4; i++) D[t][i] = 0.f;
#pragma unroll
        for (int ks = 0; ks < 8; ks++) {
            int kc = ks * 16 + 2 * tg;
            FRAG_A(Wh, Wl, 0, kc)
            (void)0;
            // A rows are r0-based:
            ah0 = ldsm(Wh, r0 + g, kc); ah1 = ldsm(Wh, r0 + g + 8, kc);
            ah2 = ldsm(Wh, r0 + g, kc + 8); ah3 = ldsm(Wh, r0 + g + 8, kc + 8);
            al0 = ldsm(Wl, r0 + g, kc); al1 = ldsm(Wl, r0 + g + 8, kc);
            al2 = ldsm(Wl, r0 + g, kc + 8); al3 = ldsm(Wl, r0 + g + 8, kc + 8);
#pragma unroll
            for (int t = 0; t < 16; t++) {
                int col = t * 8 + g;
                uint32_t bh0 = ldsm(Eh, col, kc), bh1 = ldsm(Eh, col, kc + 8);
                uint32_t bl0 = ldsm(El, col, kc), bl1 = ldsm(El, col, kc + 8);
                mma_f16(D[t], ah0, ah1, ah2, ah3, bh0, bh1);
                mma_f16(D[t], ah0, ah1, ah2, ah3, bl0, bl1);
                mma_f16(D[t], al0, al1, al2, al3, bh0, bh1);
            }
        }
        __syncthreads();   // all XT reads done before E overwrites

        // exp epilogue -> E tiles + z partials
#pragma unroll
        for (int t = 0; t < 16; t++) {
            int c0 = t * 8 + 2 * tg;
            float e0 = __expf(D[t][0]), e1 = __expf(D[t][1]);
            float e2 = __expf(D[t][2]), e3 = __expf(D[t][3]);
            zacc0 += e0 + e1; zacc8 += e2 + e3;
            __half h0, l0, h1, l1;
            split_h(e0, h0, l0); split_h(e1, h1, l1);
            *(uint32_t*)&Eh[(r0 + g) * PH + c0] = pck(h0, h1);
            *(uint32_t*)&El[(r0 + g) * PH + c0] = pck(l0, l1);
            split_h(e2, h0, l0); split_h(e3, h1, l1);
            *(uint32_t*)&Eh[(r0 + g + 8) * PH + c0] = pck(h0, h1);
            *(uint32_t*)&El[(r0 + g + 8) * PH + c0] = pck(l0, l1);
        }
        __syncthreads();

        // stage 2: SD += E @ X^T  (A = E[r][n], B = XN[c][n], k=n)
#pragma unroll
        for (int ks = 0; ks < 8; ks++) {
            int kc = ks * 16 + 2 * tg;
            uint32_t ah0 = ldsm(Eh, r0 + g, kc), ah1 = ldsm(Eh, r0 + g + 8, kc);
            uint32_t ah2 = ldsm(Eh, r0 + g, kc + 8), ah3 = ldsm(Eh, r0 + g + 8, kc + 8);
            uint32_t al0 = ldsm(El, r0 + g, kc), al1 = ldsm(El, r0 + g + 8, kc);
            uint32_t al2 = ldsm(El, r0 + g, kc + 8), al3 = ldsm(El, r0 + g + 8, kc + 8);
#pragma unroll
            for (int t = 0; t < 16; t++) {
                int col = t * 8 + g;
                uint32_t bh0 = ldsm(Nh, col, kc), bh1 = ldsm(Nh, col, kc + 8);
                uint32_t bl0 = ldsm(Nl, col, kc), bl1 = ldsm(Nl, col, kc + 8);
                mma_f16(SD[t], ah0, ah1, ah2, ah3, bh0, bh1);
                mma_f16(SD[t], ah0, ah1, ah2, ah3, bl0, bl1);
                mma_f16(SD[t], al0, al1, al2, al3, bh0, bh1);
            }
        }
    }

    // writeback S and Z
#pragma unroll
    for (int t = 0; t < 16; t++) {
        int c0 = t * 8 + 2 * tg;
        *(float2*)&g_Spart[b][blk][r0 + g][c0]     = make_float2(SD[t][0], SD[t][1]);
        *(float2*)&g_Spart[b][blk][r0 + g + 8][c0] = make_float2(SD[t][2], SD[t][3]);
    }
    zacc0 += __shfl_xor_sync(0xFFFFFFFF, zacc0, 1);
    zacc0 += __shfl_xor_sync(0xFFFFFFFF, zacc0, 2);
    zacc8 += __shfl_xor_sync(0xFFFFFFFF, zacc8, 1);
    zacc8 += __shfl_xor_sync(0xFFFFFFFF, zacc8, 2);
    if (tg == 0) {
        g_Zpart[b][blk][r0 + g]     = zacc0;
        g_Zpart[b][blk][r0 + g + 8] = zacc8;
    }
}

// ---------------- KR ----------------
__global__ void __launch_bounds__(128)
kr_kernel() {
    const int b = blockIdx.x >> 7, r = blockIdx.x & 127, c = threadIdx.x;
    float z = 0.f, s = 0.f;
    for (int p = 0; p < K1_NBLK; p++) z += g_Zpart[b][p][r];
    for (int p = 0; p < K1_NBLK; p++) s += g_Spart[b][p][r][c];
    g_Shat[b][r][c] = s / z;
}

// ---------------- K2 ----------------
__global__ void __launch_bounds__(128)
k2_kernel(const float* __restrict__ wqkv, const float* __restrict__ wout) {
    const int b = blockIdx.x >> 2, h = blockIdx.x & 3, tid = threadIdx.x;
    __shared__ float Sh[32][129], Wv[32][129], ctx[32][33];
    for (int i = tid; i < 32 * 128; i += 128) {
        int d = i >> 7, c = i & 127;
        Sh[d][c] = g_Shat[b][h * 32 + d][c];
        Wv[d][c] = wqkv[(256 + h * 32 + d) * 128 + c];
    }
    __syncthreads();
    for (int u = tid; u < 1024; u += 128) {
        int d = u >> 5, e = u & 31;
        float s = 0.f;
#pragma unroll 4
        for (int c = 0; c < 128; c++) s += Sh[d][c] * Wv[e][c];
        ctx[d][e] = s;
    }
    __syncthreads();
    float wo[32];
#pragma unroll
    for (int e = 0; e < 32; e++) wo[e] = wout[tid * 128 + h * 32 + e];
    for (int d = 0; d < 32; d++) {
        float s = 0.f;
#pragma unroll
        for (int e = 0; e < 32; e++) s += wo[e] * ctx[d][e];
        g_C2[b][tid][h * 32 + d] = s;
    }
}

// ---------------- K3 ----------------
__global__ void __launch_bounds__(256)
k3_kernel(const float* __restrict__ wqkv) {
    const int b = blockIdx.x, ch = blockIdx.y, zg = blockIdx.z, tid = threadIdx.x;
    __shared__ float C2s[32][129], Wqs[128][32];
    for (int i = tid; i < 32 * 128; i += 256) {
        int r = i >> 7, c = i & 127;
        C2s[r][c] = g_C2[b][zg * 32 + r][c];
    }
    for (int i = tid; i < 128 * 32; i += 256) {
        int j = i >> 5, cc = i & 31;
        Wqs[j][cc] = wqkv[j * 128 + ch * 32 + cc];
    }
    __syncthreads();
    const int ol = tid & 31, cg = tid >> 5;
    float acc[4] = {0.f, 0.f, 0.f, 0.f};
#pragma unroll 4
    for (int j = 0; j < 128; j++) {
        float a = C2s[ol][j];
#pragma unroll
        for (int i = 0; i < 4; i++) acc[i] += a * Wqs[j][cg * 4 + i];
    }
    *(float4*)&g_A[b][zg * 32 + ol][ch * 32 + cg * 4] = make_float4(acc[0], acc[1], acc[2], acc[3]);
}

// ---------------- K4: y = A@x + b ----------------
#define SM4_AH 0
#define SM4_AL (128 * PH)
#define SM4_XH (2 * 128 * PH)
#define SM4_XL (3 * 128 * PH)
#define SMEM_K4 (4 * 128 * PH * 2)   // 139264 B

__global__ void __launch_bounds__(256, 1)
k4_kernel(const float* __restrict__ x, const float* __restrict__ bias, float* __restrict__ y) {
    extern __shared__ __half smh[];
    __half* Ah = smh + SM4_AH; __half* Al = smh + SM4_AL;
    __half* Xh = smh + SM4_XH; __half* Xl = smh + SM4_XL;

    const int tid = threadIdx.x, lane = tid & 31;
    const int g = lane >> 2, tg = lane & 3;
    const int r0 = (tid >> 5) * 16;
    const int b = blockIdx.y, blk = blockIdx.x;
    const int n0 = blk * 128;
    const float* xb = x + (size_t)b * CC * NN;
    float* yb = y + (size_t)b * CC * NN;

    load_mat(&g_A[b][0][0], Ah, Al, tid);
    load_x<false>(xb, n0, Xh, Xl, 0, 0, tid);
    __syncthreads();

    float D[16][4];
#pragma unroll
    for (int t = 0; t < 16; t++)
#pragma unroll
        for (int i = 0; i < 4; i++) D[t][i] = 0.f;

#pragma unroll
    for (int ks = 0; ks < 8; ks++) {
        int kc = ks * 16 + 2 * tg;
        uint32_t ah0 = ldsm(Ah, r0 + g, kc), ah1 = ldsm(Ah, r0 + g + 8, kc);
        uint32_t ah2 = ldsm(Ah, r0 + g, kc + 8), ah3 = ldsm(Ah, r0 + g + 8, kc + 8);
        uint32_t al0 = ldsm(Al, r0 + g, kc), al1 = ldsm(Al, r0 + g + 8, kc);
        uint32_t al2 = ldsm(Al, r0 + g, kc + 8), al3 = ldsm(Al, r0 + g + 8, kc + 8);
#pragma unroll
        for (int t = 0; t < 16; t++) {
            int col = t * 8 + g;
            uint32_t bh0 = ldsm(Xh, col, kc), bh1 = ldsm(Xh, col, kc + 8);
            uint32_t bl0 = ldsm(Xl, col, kc), bl1 = ldsm(Xl, col, kc + 8);
            mma_f16(D[t], ah0, ah1, ah2, ah3, bh0, bh1);
            mma_f16(D[t], ah0, ah1, ah2, ah3, bl0, bl1);
            mma_f16(D[t], al0, al1, al2, al3, bh0, bh1);
        }
    }

    const float bo  = bias[r0 + g];
    const float bo8 = bias[r0 + g + 8];
#pragma unroll
    for (int t = 0; t < 16; t++) {
        int c0 = t * 8 + 2 * tg;
        *(float2*)&yb[(size_t)(r0 + g) * NN + n0 + c0] =
            make_float2(D[t][0] + bo, D[t][1] + bo);
        *(float2*)&yb[(size_t)(r0 + g + 8) * NN + n0 + c0] =
            make_float2(D[t][2] + bo8, D[t][3] + bo8);
    }
}

// ---------------- launch ----------------
extern "C" void kernel_launch(void* const* d_in, const int* in_sizes, int n_in,
                              void* d_out, int out_size) {
    (void)in_sizes; (void)n_in; (void)out_size;
    const float* x    = (const float*)d_in[0];
    const float* wqkv = (const float*)d_in[1];
    const float* wout = (const float*)d_in[2];
    const float* bout = (const float*)d_in[3];
    float* y = (float*)d_out;

    cudaFuncSetAttribute(k1_kernel, cudaFuncAttributeMaxDynamicSharedMemorySize, SMEM_K1);
    cudaFuncSetAttribute(k4_kernel, cudaFuncAttributeMaxDynamicSharedMemorySize, SMEM_K4);

    k1_kernel<<<dim3(K1_NBLK, BB), 256, SMEM_K1>>>(x, wqkv);
    kr_kernel<<<BB * 128, 128>>>();
    k2_kernel<<<BB * 4, 128>>>(wqkv, wout);
    k3_kernel<<<dim3(BB, 4, 4), 256>>>(wqkv);
    k4_kernel<<<dim3(128, BB), 256, SMEM_K4>>>(x, bout, y);
}